// round 14
// baseline (speedup 1.0000x reference)
#include <cuda_runtime.h>
#include <cuda_fp16.h>
#include <math.h>
#include <cstdint>

// ---------------------------------------------------------------------------
// Problem constants
// ---------------------------------------------------------------------------
#define BATCH      8192
#define IN_DIM     2048
#define OUT_DIM    1000
#define DEPTH      10
#define NUM_INNER  1023
#define NUM_LEAF   1024
#define ALLPP_COLS 2047

#define LOGITS_OFF 0
#define MU_OFF     (BATCH * OUT_DIM)
#define PEN_OFF    (MU_OFF + BATCH * NUM_LEAF)
#define ALLPP_OFF  (PEN_OFF + 1)

// ---------------------------------------------------------------------------
// Scratch
// ---------------------------------------------------------------------------
__device__ __align__(128) __half g_Xh[BATCH * IN_DIM];   // fp16 X; later fp16 mu (32 MB)
__device__ __align__(128) float  g_P[BATCH * 1024];      // sigmoid outputs (32 MB)
__device__ __align__(128) __half g_Bih[1024 * 2048];     // fp16 W_inner[:,1:] (4 MB)
__device__ __align__(128) __half g_Blh[1024 * 1024];     // fp16 padded W_leaf (2 MB)
__device__ __align__(128) float  g_bias[1024];
__device__ float g_num[1024];
__device__ float g_den[1024];

// ---------------------------------------------------------------------------
// Helpers
// ---------------------------------------------------------------------------
__device__ __forceinline__ uint32_t smem_u32(const void* p) {
    uint32_t a;
    asm("{ .reg .u64 t; cvta.to.shared.u64 t, %1; cvt.u32.u64 %0, t; }"
        : "=r"(a) : "l"(p));
    return a;
}
__device__ __forceinline__ void cp16(uint32_t dst, const void* src) {
    asm volatile("cp.async.cg.shared.global [%0], [%1], 16;"
                 :: "r"(dst), "l"(src));
}
__device__ __forceinline__ void ldsm4(uint32_t& r0, uint32_t& r1,
                                      uint32_t& r2, uint32_t& r3, uint32_t addr) {
    asm volatile("ldmatrix.sync.aligned.m8n8.x4.shared.b16 {%0,%1,%2,%3}, [%4];"
                 : "=r"(r0), "=r"(r1), "=r"(r2), "=r"(r3) : "r"(addr));
}

// ---------------------------------------------------------------------------
// fp16 mma.sync GEMM (unchanged from R13 best): BM=128, BN=128, BK=64,
// 3 stages, 256 threads = 8 warps 2(M)x4(N), 2 CTAs/SM, ldmatrix.x4.
// ---------------------------------------------------------------------------
#define BM 128
#define BN 128
#define BK 64
#define STAGES 3
#define NTHR 256
#define ROW_H 72                             // BK halves + 8 pad (144 B rows)
#define A_TILE_H (BM * ROW_H)                // 9216 halves
#define B_TILE_H (BN * ROW_H)                // 9216 halves
#define GEMM_SMEM (STAGES * (A_TILE_H + B_TILE_H) * 2)   // 110592 B

template <bool SIG>
__global__ __launch_bounds__(NTHR, 2)
void mgemm(const __half* __restrict__ A, int lda,
           const __half* __restrict__ B, int ldb,
           float* __restrict__ C, int ldc, int nstore, int K)
{
    extern __shared__ __half smh[];
    __half* Asm = smh;
    __half* Bsm = smh + STAGES * A_TILE_H;

    const int tid  = threadIdx.x;
    const int lane = tid & 31;
    const int warp = tid >> 5;                // 0..7
    const int g  = lane >> 2;
    const int t  = lane & 3;
    const int wm = warp & 1;                  // M offset 64*wm
    const int wn = warp >> 1;                 // N offset 32*wn
    const int bm = blockIdx.y * BM;
    const int bn = blockIdx.x * BN;

    const int a_lrow = lane & 15;
    const int a_lcol = (lane >> 4) * 8;
    const int b_lrow = ((lane >> 4) * 8) + (lane & 7);
    const int b_lcol = ((lane >> 3) & 1) * 8;

    float c[4][4][4];
#pragma unroll
    for (int i = 0; i < 4; i++)
#pragma unroll
        for (int j = 0; j < 4; j++)
#pragma unroll
            for (int e = 0; e < 4; e++) c[i][j][e] = 0.f;

    const int nchunk = K / BK;

    auto load_stage = [&](int ic, int s) {
        __half* as = Asm + s * A_TILE_H;
        __half* bs = Bsm + s * B_TILE_H;
        const int k0 = ic * BK;
#pragma unroll
        for (int it = 0; it < 4; ++it) {
            int seg = tid + it * NTHR;
            int row = seg >> 3, u = seg & 7;
            cp16(smem_u32(as + row * ROW_H + u * 8),
                 A + (size_t)(bm + row) * lda + k0 + u * 8);
        }
#pragma unroll
        for (int it = 0; it < 4; ++it) {
            int seg = tid + it * NTHR;
            int row = seg >> 3, u = seg & 7;
            cp16(smem_u32(bs + row * ROW_H + u * 8),
                 B + (size_t)(bn + row) * ldb + k0 + u * 8);
        }
    };

#pragma unroll
    for (int ic = 0; ic < STAGES - 1; ++ic) {
        load_stage(ic, ic);
        asm volatile("cp.async.commit_group;" ::: "memory");
    }

    for (int i = 0; i < nchunk; ++i) {
        asm volatile("cp.async.wait_group 1;" ::: "memory");
        __syncthreads();

        int pf = i + STAGES - 1;
        if (pf < nchunk) load_stage(pf, pf % STAGES);
        asm volatile("cp.async.commit_group;" ::: "memory");

        const int s = i % STAGES;
        const __half* as = Asm + s * A_TILE_H + (wm * 64) * ROW_H;
        const __half* bs = Bsm + s * B_TILE_H + (wn * 32) * ROW_H;
        const uint32_t abase = smem_u32(as + a_lrow * ROW_H + a_lcol);
        const uint32_t bbase = smem_u32(bs + b_lrow * ROW_H + b_lcol);

#pragma unroll
        for (int ks = 0; ks < 4; ++ks) {
            uint32_t a[4][4], b[4][2];
#pragma unroll
            for (int mt = 0; mt < 4; ++mt)
                ldsm4(a[mt][0], a[mt][1], a[mt][2], a[mt][3],
                      abase + (mt * 16 * ROW_H + ks * 16) * 2);
#pragma unroll
            for (int np = 0; np < 2; ++np)
                ldsm4(b[2 * np][0], b[2 * np][1], b[2 * np + 1][0], b[2 * np + 1][1],
                      bbase + (np * 16 * ROW_H + ks * 16) * 2);
#pragma unroll
            for (int mt = 0; mt < 4; ++mt)
#pragma unroll
                for (int nt = 0; nt < 4; ++nt) {
                    asm volatile(
                        "mma.sync.aligned.m16n8k16.row.col.f32.f16.f16.f32 "
                        "{%0,%1,%2,%3}, {%4,%5,%6,%7}, {%8,%9}, {%0,%1,%2,%3};"
                        : "+f"(c[mt][nt][0]), "+f"(c[mt][nt][1]),
                          "+f"(c[mt][nt][2]), "+f"(c[mt][nt][3])
                        : "r"(a[mt][0]), "r"(a[mt][1]), "r"(a[mt][2]), "r"(a[mt][3]),
                          "r"(b[nt][0]), "r"(b[nt][1]));
                }
        }
    }

    // ---- epilogue ----
#pragma unroll
    for (int mt = 0; mt < 4; ++mt) {
        const int r0 = bm + wm * 64 + mt * 16 + g;
#pragma unroll
        for (int nt = 0; nt < 4; ++nt) {
            const int col = bn + wn * 32 + nt * 8 + t * 2;
            if (col < nstore) {
                float v0 = c[mt][nt][0], v1 = c[mt][nt][1];
                float v2 = c[mt][nt][2], v3 = c[mt][nt][3];
                if (SIG) {
                    const float b0 = g_bias[col], b1 = g_bias[col + 1];
                    v0 = 1.f / (1.f + __expf(-(v0 + b0)));
                    v1 = 1.f / (1.f + __expf(-(v1 + b1)));
                    v2 = 1.f / (1.f + __expf(-(v2 + b0)));
                    v3 = 1.f / (1.f + __expf(-(v3 + b1)));
                }
                if (col + 1 < nstore) {
                    *(float2*)&C[(size_t)r0 * ldc + col]       = make_float2(v0, v1);
                    *(float2*)&C[(size_t)(r0 + 8) * ldc + col] = make_float2(v2, v3);
                } else {
                    C[(size_t)r0 * ldc + col]       = v0;
                    C[(size_t)(r0 + 8) * ldc + col] = v2;
                }
            }
        }
    }
}

// ---------------------------------------------------------------------------
// Fused prep (unchanged)
// ---------------------------------------------------------------------------
__global__ void prep_all_kernel(const float* __restrict__ X,
                                const float* __restrict__ Wi,
                                const float* __restrict__ Wl) {
    int idx = blockIdx.x * blockDim.x + threadIdx.x;
    if (idx >= 1024 * 2048) return;
    if (idx < 1024) { g_num[idx] = 0.f; g_den[idx] = 0.f; }

    {
        int n = idx >> 11;
        int k = idx & 2047;
        float v = 0.f;
        if (n < NUM_INNER) v = Wi[(size_t)n * (IN_DIM + 1) + 1 + k];
        g_Bih[idx] = __float2half_rn(v);
        if (k == 0) g_bias[n] = (n < NUM_INNER) ? Wi[(size_t)n * (IN_DIM + 1)] : 0.f;
    }
    {
#pragma unroll
        for (int r = 0; r < 2; ++r) {
            int i4 = idx + r * (1024 * 2048);
            float4 v = ((const float4*)X)[i4];
            __half2 h0 = __floats2half2_rn(v.x, v.y);
            __half2 h1 = __floats2half2_rn(v.z, v.w);
            ((__half2*)g_Xh)[i4 * 2]     = h0;
            ((__half2*)g_Xh)[i4 * 2 + 1] = h1;
        }
    }
    if (idx < 1024 * 1024) {
        int n = idx >> 10;
        int k = idx & 1023;
        float v = (n < OUT_DIM) ? Wl[(size_t)n * NUM_LEAF + k] : 0.f;
        g_Blh[idx] = __float2half_rn(v);
    }
}

// ---------------------------------------------------------------------------
// Cascade + fused penalty accumulation.
// 8 rows/block, 512 threads, 96 KB dynamic smem.
// ---------------------------------------------------------------------------
#define CROWS 8
#define CTHR  512
#define CASCADE_SMEM ((CROWS * 1024 + CROWS * 2048) * 4)   // 98304 B

__global__ __launch_bounds__(CTHR)
void cascade_kernel(const float* __restrict__ P, float* __restrict__ mu_out,
                    float* __restrict__ allpp)
{
    extern __shared__ float csm[];
    float (*p_sh)[1024] = (float(*)[1024])csm;
    float (*ap)[2048]   = (float(*)[2048])(csm + CROWS * 1024);

    const int tid = threadIdx.x;
    const int b0 = blockIdx.x * CROWS;

#pragma unroll
    for (int r = 0; r < CROWS; r++)
        for (int j = tid; j < NUM_INNER; j += CTHR)
            p_sh[r][j] = P[(size_t)(b0 + r) * 1024 + j];

    if (tid < CROWS) ap[tid][0] = 1.f;
    __syncthreads();

    for (int lvl = 0; lvl < DEPTH; lvl++) {
        const int n = 1 << lvl;
        const int start = n - 1;
        const int outbase = 2 * n - 1;
        const int total = CROWS * 2 * n;
        for (int idx = tid; idx < total; idx += CTHR) {
            int r  = idx / (2 * n);
            int jj = idx - r * (2 * n);
            int j  = jj >> 1;
            int cc = jj & 1;
            float pm = p_sh[r][start + j];
            float v  = ap[r][start + j] * (cc ? pm : (1.f - pm));
            ap[r][outbase + jj] = v;
        }
        __syncthreads();
    }

    for (int idx = tid; idx < CROWS * NUM_LEAF; idx += CTHR) {
        int r = idx >> 10, j = idx & 1023;
        float v = ap[r][1023 + j];
        mu_out[(size_t)(b0 + r) * NUM_LEAF + j] = v;
        g_Xh[(size_t)(b0 + r) * 1024 + j] = __float2half_rn(v);
    }
    for (int idx = tid; idx < CROWS * ALLPP_COLS; idx += CTHR) {
        int r = idx / ALLPP_COLS, cix = idx - r * ALLPP_COLS;
        allpp[(size_t)(b0 + r) * ALLPP_COLS + cix] = ap[r][cix];
    }
    for (int k = tid; k < NUM_INNER; k += CTHR) {
        float sn = 0.f, sd = 0.f;
#pragma unroll
        for (int r = 0; r < CROWS; r++) {
            float m = ap[r][k];
            sn += p_sh[r][k] * m;
            sd += m;
        }
        atomicAdd(&g_num[k], sn);
        atomicAdd(&g_den[k], sd);
    }
}

// ---------------------------------------------------------------------------
// Penalty finalization: 1024 threads, one node each.
// ---------------------------------------------------------------------------
__global__ __launch_bounds__(1024)
void pen_final_kernel(float* __restrict__ pen_out)
{
    __shared__ float red[1024];
    const int tid = threadIdx.x;
    float local = 0.f;
    if (tid < NUM_INNER) {
        float alpha = g_num[tid] / g_den[tid];
        float pen = logf(alpha) + logf(1.f - alpha);
        if (!isfinite(pen)) pen = 0.f;
        int lvl = 31 - __clz(tid + 1);
        float w = ldexpf(0.5f, -lvl);
        local = -w * pen;
    }
    red[tid] = local;
    __syncthreads();
    for (int s = 512; s > 0; s >>= 1) {
        if (tid < s) red[tid] += red[tid + s];
        __syncthreads();
    }
    if (tid == 0) pen_out[0] = red[0];
}

// ---------------------------------------------------------------------------
// Launch
// ---------------------------------------------------------------------------
extern "C" void kernel_launch(void* const* d_in, const int* in_sizes, int n_in,
                              void* d_out, int out_size)
{
    const float* X  = (const float*)d_in[0];
    const float* Wi = (const float*)d_in[1];
    const float* Wl = (const float*)d_in[2];
    float* out = (float*)d_out;

    float* logits = out + LOGITS_OFF;
    float* mu     = out + MU_OFF;
    float* pen    = out + PEN_OFF;
    float* allpp  = out + ALLPP_OFF;

    __half* Xh = nullptr;
    float*  P  = nullptr;
    __half* Bi = nullptr;
    __half* Bl = nullptr;
    cudaGetSymbolAddress((void**)&Xh, g_Xh);
    cudaGetSymbolAddress((void**)&P,  g_P);
    cudaGetSymbolAddress((void**)&Bi, g_Bih);
    cudaGetSymbolAddress((void**)&Bl, g_Blh);

    cudaFuncSetAttribute(mgemm<true>,
                         cudaFuncAttributeMaxDynamicSharedMemorySize, GEMM_SMEM);
    cudaFuncSetAttribute(mgemm<false>,
                         cudaFuncAttributeMaxDynamicSharedMemorySize, GEMM_SMEM);
    cudaFuncSetAttribute(cascade_kernel,
                         cudaFuncAttributeMaxDynamicSharedMemorySize, CASCADE_SMEM);

    prep_all_kernel<<<(1024 * 2048 + 255) / 256, 256>>>(X, Wi, Wl);

    // GEMM1: P = sigmoid(bias + Xh @ g_Bih^T)   [8192 x 1024], K=2048
    {
        dim3 grid(1024 / BN, BATCH / BM);
        mgemm<true><<<grid, NTHR, GEMM_SMEM>>>(
            Xh, IN_DIM, Bi, IN_DIM, P, 1024, 1024, IN_DIM);
    }

    cascade_kernel<<<BATCH / CROWS, CTHR, CASCADE_SMEM>>>(P, mu, allpp);

    pen_final_kernel<<<1, 1024>>>(pen);

    // GEMM2: logits = mu_h @ g_Blh^T   [8192 x 1000], K=1024
    {
        dim3 grid(1024 / BN, BATCH / BM);
        mgemm<false><<<grid, NTHR, GEMM_SMEM>>>(
            Xh, NUM_LEAF, Bl, NUM_LEAF, logits, OUT_DIM, OUT_DIM, NUM_LEAF);
    }
}

// round 15
// speedup vs baseline: 1.0398x; 1.0398x over previous
#include <cuda_runtime.h>
#include <cuda_fp16.h>
#include <math.h>
#include <cstdint>

// ---------------------------------------------------------------------------
// Problem constants
// ---------------------------------------------------------------------------
#define BATCH      8192
#define IN_DIM     2048
#define OUT_DIM    1000
#define DEPTH      10
#define NUM_INNER  1023
#define NUM_LEAF   1024
#define ALLPP_COLS 2047

#define LOGITS_OFF 0
#define MU_OFF     (BATCH * OUT_DIM)
#define PEN_OFF    (MU_OFF + BATCH * NUM_LEAF)
#define ALLPP_OFF  (PEN_OFF + 1)

// ---------------------------------------------------------------------------
// Scratch
// ---------------------------------------------------------------------------
__device__ __align__(128) __half g_Xh[BATCH * IN_DIM];   // fp16 X; later fp16 mu (32 MB)
__device__ __align__(128) float  g_P[BATCH * 1024];      // sigmoid outputs (32 MB)
__device__ __align__(128) __half g_Bih[1024 * 2048];     // fp16 W_inner[:,1:] (4 MB)
__device__ __align__(128) __half g_Blh[1024 * 1024];     // fp16 padded W_leaf (2 MB)
__device__ __align__(128) float  g_bias[1024];
__device__ float g_num[1024];
__device__ float g_den[1024];

// ---------------------------------------------------------------------------
// Helpers
// ---------------------------------------------------------------------------
__device__ __forceinline__ uint32_t smem_u32(const void* p) {
    uint32_t a;
    asm("{ .reg .u64 t; cvta.to.shared.u64 t, %1; cvt.u32.u64 %0, t; }"
        : "=r"(a) : "l"(p));
    return a;
}
__device__ __forceinline__ void cp16(uint32_t dst, const void* src) {
    asm volatile("cp.async.cg.shared.global [%0], [%1], 16;"
                 :: "r"(dst), "l"(src));
}
__device__ __forceinline__ void ldsm4(uint32_t& r0, uint32_t& r1,
                                      uint32_t& r2, uint32_t& r3, uint32_t addr) {
    asm volatile("ldmatrix.sync.aligned.m8n8.x4.shared.b16 {%0,%1,%2,%3}, [%4];"
                 : "=r"(r0), "=r"(r1), "=r"(r2), "=r"(r3) : "r"(addr));
}

// ---------------------------------------------------------------------------
// fp16 mma.sync GEMM (R13 best): BM=128, BN=128, BK=64, 3 stages,
// 256 threads = 8 warps 2(M)x4(N), 2 CTAs/SM, ldmatrix.x4.
// PEN template param: last block (linear id == grid-1 when PEN) runs the
// penalty finalization instead of GEMM work.
// ---------------------------------------------------------------------------
#define BM 128
#define BN 128
#define BK 64
#define STAGES 3
#define NTHR 256
#define ROW_H 72                             // BK halves + 8 pad (144 B rows)
#define A_TILE_H (BM * ROW_H)                // 9216 halves
#define B_TILE_H (BN * ROW_H)                // 9216 halves
#define GEMM_SMEM (STAGES * (A_TILE_H + B_TILE_H) * 2)   // 110592 B
#define GRID_X 8                              // 1024 / BN

__device__ void pen_final_body(float* pen_out) {
    __shared__ float red[256];
    const int tid = threadIdx.x;
    float local = 0.f;
    for (int k = tid; k < NUM_INNER; k += 256) {
        float alpha = g_num[k] / g_den[k];
        float pen = logf(alpha) + logf(1.f - alpha);
        if (!isfinite(pen)) pen = 0.f;
        int lvl = 31 - __clz(k + 1);
        float w = ldexpf(0.5f, -lvl);
        local -= w * pen;
    }
    red[tid] = local;
    __syncthreads();
    for (int s = 128; s > 0; s >>= 1) {
        if (tid < s) red[tid] += red[tid + s];
        __syncthreads();
    }
    if (tid == 0) pen_out[0] = red[0];
}

template <bool SIG, bool PEN>
__global__ __launch_bounds__(NTHR, 2)
void mgemm(const __half* __restrict__ A, int lda,
           const __half* __restrict__ B, int ldb,
           float* __restrict__ C, int ldc, int nstore, int K,
           float* __restrict__ pen_out)
{
    if (PEN && blockIdx.x == gridDim.x - 1) {
        pen_final_body(pen_out);
        return;
    }
    const int bx = blockIdx.x % GRID_X;
    const int by = blockIdx.x / GRID_X;

    extern __shared__ __half smh[];
    __half* Asm = smh;
    __half* Bsm = smh + STAGES * A_TILE_H;

    const int tid  = threadIdx.x;
    const int lane = tid & 31;
    const int warp = tid >> 5;                // 0..7
    const int g  = lane >> 2;
    const int t  = lane & 3;
    const int wm = warp & 1;                  // M offset 64*wm
    const int wn = warp >> 1;                 // N offset 32*wn
    const int bm = by * BM;
    const int bn = bx * BN;

    const int a_lrow = lane & 15;
    const int a_lcol = (lane >> 4) * 8;
    const int b_lrow = ((lane >> 4) * 8) + (lane & 7);
    const int b_lcol = ((lane >> 3) & 1) * 8;

    float c[4][4][4];
#pragma unroll
    for (int i = 0; i < 4; i++)
#pragma unroll
        for (int j = 0; j < 4; j++)
#pragma unroll
            for (int e = 0; e < 4; e++) c[i][j][e] = 0.f;

    const int nchunk = K / BK;

    auto load_stage = [&](int ic, int s) {
        __half* as = Asm + s * A_TILE_H;
        __half* bs = Bsm + s * B_TILE_H;
        const int k0 = ic * BK;
#pragma unroll
        for (int it = 0; it < 4; ++it) {
            int seg = tid + it * NTHR;
            int row = seg >> 3, u = seg & 7;
            cp16(smem_u32(as + row * ROW_H + u * 8),
                 A + (size_t)(bm + row) * lda + k0 + u * 8);
        }
#pragma unroll
        for (int it = 0; it < 4; ++it) {
            int seg = tid + it * NTHR;
            int row = seg >> 3, u = seg & 7;
            cp16(smem_u32(bs + row * ROW_H + u * 8),
                 B + (size_t)(bn + row) * ldb + k0 + u * 8);
        }
    };

#pragma unroll
    for (int ic = 0; ic < STAGES - 1; ++ic) {
        load_stage(ic, ic);
        asm volatile("cp.async.commit_group;" ::: "memory");
    }

    for (int i = 0; i < nchunk; ++i) {
        asm volatile("cp.async.wait_group 1;" ::: "memory");
        __syncthreads();

        int pf = i + STAGES - 1;
        if (pf < nchunk) load_stage(pf, pf % STAGES);
        asm volatile("cp.async.commit_group;" ::: "memory");

        const int s = i % STAGES;
        const __half* as = Asm + s * A_TILE_H + (wm * 64) * ROW_H;
        const __half* bs = Bsm + s * B_TILE_H + (wn * 32) * ROW_H;
        const uint32_t abase = smem_u32(as + a_lrow * ROW_H + a_lcol);
        const uint32_t bbase = smem_u32(bs + b_lrow * ROW_H + b_lcol);

#pragma unroll
        for (int ks = 0; ks < 4; ++ks) {
            uint32_t a[4][4], b[4][2];
#pragma unroll
            for (int mt = 0; mt < 4; ++mt)
                ldsm4(a[mt][0], a[mt][1], a[mt][2], a[mt][3],
                      abase + (mt * 16 * ROW_H + ks * 16) * 2);
#pragma unroll
            for (int np = 0; np < 2; ++np)
                ldsm4(b[2 * np][0], b[2 * np][1], b[2 * np + 1][0], b[2 * np + 1][1],
                      bbase + (np * 16 * ROW_H + ks * 16) * 2);
#pragma unroll
            for (int mt = 0; mt < 4; ++mt)
#pragma unroll
                for (int nt = 0; nt < 4; ++nt) {
                    asm volatile(
                        "mma.sync.aligned.m16n8k16.row.col.f32.f16.f16.f32 "
                        "{%0,%1,%2,%3}, {%4,%5,%6,%7}, {%8,%9}, {%0,%1,%2,%3};"
                        : "+f"(c[mt][nt][0]), "+f"(c[mt][nt][1]),
                          "+f"(c[mt][nt][2]), "+f"(c[mt][nt][3])
                        : "r"(a[mt][0]), "r"(a[mt][1]), "r"(a[mt][2]), "r"(a[mt][3]),
                          "r"(b[nt][0]), "r"(b[nt][1]));
                }
        }
    }

    // ---- epilogue ----
#pragma unroll
    for (int mt = 0; mt < 4; ++mt) {
        const int r0 = bm + wm * 64 + mt * 16 + g;
#pragma unroll
        for (int nt = 0; nt < 4; ++nt) {
            const int col = bn + wn * 32 + nt * 8 + t * 2;
            if (col < nstore) {
                float v0 = c[mt][nt][0], v1 = c[mt][nt][1];
                float v2 = c[mt][nt][2], v3 = c[mt][nt][3];
                if (SIG) {
                    const float b0 = g_bias[col], b1 = g_bias[col + 1];
                    v0 = 1.f / (1.f + __expf(-(v0 + b0)));
                    v1 = 1.f / (1.f + __expf(-(v1 + b1)));
                    v2 = 1.f / (1.f + __expf(-(v2 + b0)));
                    v3 = 1.f / (1.f + __expf(-(v3 + b1)));
                }
                if (col + 1 < nstore) {
                    *(float2*)&C[(size_t)r0 * ldc + col]       = make_float2(v0, v1);
                    *(float2*)&C[(size_t)(r0 + 8) * ldc + col] = make_float2(v2, v3);
                } else {
                    C[(size_t)r0 * ldc + col]       = v0;
                    C[(size_t)(r0 + 8) * ldc + col] = v2;
                }
            }
        }
    }
}

// ---------------------------------------------------------------------------
// Fused prep
// ---------------------------------------------------------------------------
__global__ void prep_all_kernel(const float* __restrict__ X,
                                const float* __restrict__ Wi,
                                const float* __restrict__ Wl) {
    int idx = blockIdx.x * blockDim.x + threadIdx.x;
    if (idx >= 1024 * 2048) return;
    if (idx < 1024) { g_num[idx] = 0.f; g_den[idx] = 0.f; }

    {
        int n = idx >> 11;
        int k = idx & 2047;
        float v = 0.f;
        if (n < NUM_INNER) v = Wi[(size_t)n * (IN_DIM + 1) + 1 + k];
        g_Bih[idx] = __float2half_rn(v);
        if (k == 0) g_bias[n] = (n < NUM_INNER) ? Wi[(size_t)n * (IN_DIM + 1)] : 0.f;
    }
    {
#pragma unroll
        for (int r = 0; r < 2; ++r) {
            int i4 = idx + r * (1024 * 2048);
            float4 v = ((const float4*)X)[i4];
            __half2 h0 = __floats2half2_rn(v.x, v.y);
            __half2 h1 = __floats2half2_rn(v.z, v.w);
            ((__half2*)g_Xh)[i4 * 2]     = h0;
            ((__half2*)g_Xh)[i4 * 2 + 1] = h1;
        }
    }
    if (idx < 1024 * 1024) {
        int n = idx >> 10;
        int k = idx & 1023;
        float v = (n < OUT_DIM) ? Wl[(size_t)n * NUM_LEAF + k] : 0.f;
        g_Blh[idx] = __float2half_rn(v);
    }
}

// ---------------------------------------------------------------------------
// Cascade + fused penalty accumulation (R13 best: 4 rows, 256 threads).
// ---------------------------------------------------------------------------
#define CROWS 4
__global__ __launch_bounds__(256)
void cascade_kernel(const float* __restrict__ P, float* __restrict__ mu_out,
                    float* __restrict__ allpp)
{
    __shared__ float p_sh[CROWS][1024];
    __shared__ float ap[CROWS][2048];

    const int tid = threadIdx.x;
    const int b0 = blockIdx.x * CROWS;

#pragma unroll
    for (int r = 0; r < CROWS; r++)
        for (int j = tid; j < NUM_INNER; j += 256)
            p_sh[r][j] = P[(size_t)(b0 + r) * 1024 + j];

    if (tid < CROWS) ap[tid][0] = 1.f;
    __syncthreads();

    for (int lvl = 0; lvl < DEPTH; lvl++) {
        const int n = 1 << lvl;
        const int start = n - 1;
        const int outbase = 2 * n - 1;
        const int total = CROWS * 2 * n;
        for (int idx = tid; idx < total; idx += 256) {
            int r  = idx / (2 * n);
            int jj = idx - r * (2 * n);
            int j  = jj >> 1;
            int cc = jj & 1;
            float pm = p_sh[r][start + j];
            float v  = ap[r][start + j] * (cc ? pm : (1.f - pm));
            ap[r][outbase + jj] = v;
        }
        __syncthreads();
    }

    for (int idx = tid; idx < CROWS * NUM_LEAF; idx += 256) {
        int r = idx >> 10, j = idx & 1023;
        float v = ap[r][1023 + j];
        mu_out[(size_t)(b0 + r) * NUM_LEAF + j] = v;
        g_Xh[(size_t)(b0 + r) * 1024 + j] = __float2half_rn(v);
    }
    for (int idx = tid; idx < CROWS * ALLPP_COLS; idx += 256) {
        int r = idx / ALLPP_COLS, cix = idx - r * ALLPP_COLS;
        allpp[(size_t)(b0 + r) * ALLPP_COLS + cix] = ap[r][cix];
    }
    for (int k = tid; k < NUM_INNER; k += 256) {
        float sn = 0.f, sd = 0.f;
#pragma unroll
        for (int r = 0; r < CROWS; r++) {
            float m = ap[r][k];
            sn += p_sh[r][k] * m;
            sd += m;
        }
        atomicAdd(&g_num[k], sn);
        atomicAdd(&g_den[k], sd);
    }
}

// ---------------------------------------------------------------------------
// Launch
// ---------------------------------------------------------------------------
extern "C" void kernel_launch(void* const* d_in, const int* in_sizes, int n_in,
                              void* d_out, int out_size)
{
    const float* X  = (const float*)d_in[0];
    const float* Wi = (const float*)d_in[1];
    const float* Wl = (const float*)d_in[2];
    float* out = (float*)d_out;

    float* logits = out + LOGITS_OFF;
    float* mu     = out + MU_OFF;
    float* pen    = out + PEN_OFF;
    float* allpp  = out + ALLPP_OFF;

    __half* Xh = nullptr;
    float*  P  = nullptr;
    __half* Bi = nullptr;
    __half* Bl = nullptr;
    cudaGetSymbolAddress((void**)&Xh, g_Xh);
    cudaGetSymbolAddress((void**)&P,  g_P);
    cudaGetSymbolAddress((void**)&Bi, g_Bih);
    cudaGetSymbolAddress((void**)&Bl, g_Blh);

    cudaFuncSetAttribute(mgemm<true, false>,
                         cudaFuncAttributeMaxDynamicSharedMemorySize, GEMM_SMEM);
    cudaFuncSetAttribute(mgemm<false, true>,
                         cudaFuncAttributeMaxDynamicSharedMemorySize, GEMM_SMEM);

    prep_all_kernel<<<(1024 * 2048 + 255) / 256, 256>>>(X, Wi, Wl);

    // GEMM1: P = sigmoid(bias + Xh @ g_Bih^T)   [8192 x 1024], K=2048
    mgemm<true, false><<<GRID_X * (BATCH / BM), NTHR, GEMM_SMEM>>>(
        Xh, IN_DIM, Bi, IN_DIM, P, 1024, 1024, IN_DIM, nullptr);

    cascade_kernel<<<BATCH / CROWS, 256>>>(P, mu, allpp);

    // GEMM2 + fused penalty finalization (extra trailing block)
    mgemm<false, true><<<GRID_X * (BATCH / BM) + 1, NTHR, GEMM_SMEM>>>(
        Xh, NUM_LEAF, Bl, NUM_LEAF, logits, OUT_DIM, OUT_DIM, NUM_LEAF, pen);
}